// round 3
// baseline (speedup 1.0000x reference)
#include <cuda_runtime.h>
#include <cuda_fp16.h>
#include <math.h>

#define BB 4
#define NN 8192
#define KK 32
#define BN (BB*NN)
#define PT 4
#define NWARP 8
#define NTASK (BN/PT)

typedef unsigned long long u64;

// scratch (device globals; no allocation)
__device__ uint2   g_F1ab[BN*32];   // per point: 32 groups {a[2L],a[2L+1],b[2L],b[2L+1]} fp16
__device__ __half2 g_F1c[BN*32];
__device__ float   g_z[BN*64];
__device__ float   g_rh[BN*64];

__device__ __forceinline__ float lrelu(float v){ return v > 0.f ? v : 0.1f*v; }
__device__ __forceinline__ float sigm(float v){ return 1.f/(1.f+expf(-v)); }
__device__ __forceinline__ u64 pk2(float lo, float hi){
    u64 d; asm("mov.b64 %0, {%1,%2};" : "=l"(d) : "f"(lo), "f"(hi)); return d;
}
__device__ __forceinline__ float2 upk(u64 v){
    float2 r; asm("mov.b64 {%0,%1}, %2;" : "=f"(r.x), "=f"(r.y) : "l"(v)); return r;
}
// Blackwell packed fp32 FMA (SASS FFMA2): two fp32 fma in one instruction.
__device__ __forceinline__ u64 ffma2(u64 a, u64 b, u64 c){
    u64 d; asm("fma.rn.f32x2 %0, %1, %2, %3;" : "=l"(d) : "l"(a), "l"(b), "l"(c)); return d;
}

// ---------------- linear2: F1ab = [h|x] @ {W1a[0], W1a[1]}, packed fp16 out ----------------
__global__ void linear2_kernel(const float* __restrict__ s0, const float* __restrict__ s1,
                               const float* __restrict__ Wa, const float* __restrict__ Wb,
                               uint2* __restrict__ oAB)
{
    extern __shared__ float sm[];
    float4* sW4 = (float4*)sm;              // 128*32 float4 = 64KB  {a0,a1,b0,b1}
    float2* sF2 = (float2*)(sm + 16384);    // NWARP*PT*128 float2 = 32KB (dup'd acts)
    int tid = threadIdx.x, w = tid>>5, L = tid&31;
    for (int i = tid; i < 4096; i += blockDim.x) {
        int c = i >> 5, l = i & 31;
        float4 wv;
        wv.x = Wa[c*64 + 2*l];   wv.y = Wa[c*64 + 2*l + 1];
        wv.z = Wb[c*64 + 2*l];   wv.w = Wb[c*64 + 2*l + 1];
        sW4[i] = wv;
    }
    __syncthreads();
    float2* f = sF2 + w*(PT*128);
    const u64* f64 = (const u64*)f;
    for (int t = blockIdx.x*NWARP + w; t < NTASK; t += gridDim.x*NWARP) {
        int p0 = t*PT;
        #pragma unroll
        for (int q = 0; q < PT; q++) {
            int p = p0 + q;
            float v0 = s0[(size_t)p*64 + L],  v1 = s0[(size_t)p*64 + 32 + L];
            float v2 = s1[(size_t)p*64 + L],  v3 = s1[(size_t)p*64 + 32 + L];
            f[q*128 + L]      = make_float2(v0, v0);
            f[q*128 + 32 + L] = make_float2(v1, v1);
            f[q*128 + 64 + L] = make_float2(v2, v2);
            f[q*128 + 96 + L] = make_float2(v3, v3);
        }
        __syncwarp();
        u64 accA[PT], accB[PT];
        #pragma unroll
        for (int q = 0; q < PT; q++) { accA[q] = 0ull; accB[q] = 0ull; }
        #pragma unroll 8
        for (int c = 0; c < 128; c++) {
            float4 wv = sW4[c*32 + L];
            u64 wa = pk2(wv.x, wv.y), wb = pk2(wv.z, wv.w);
            #pragma unroll
            for (int q = 0; q < PT; q++) {
                u64 a = f64[q*128 + c];
                accA[q] = ffma2(a, wa, accA[q]);
                accB[q] = ffma2(a, wb, accB[q]);
            }
        }
        #pragma unroll
        for (int q = 0; q < PT; q++) {
            float2 ra = upk(accA[q]), rb = upk(accB[q]);
            __half2 ha = __floats2half2_rn(ra.x, ra.y);
            __half2 hb = __floats2half2_rn(rb.x, rb.y);
            uint2 o;
            o.x = *(const unsigned int*)&ha;
            o.y = *(const unsigned int*)&hb;
            oAB[(size_t)(p0+q)*32 + L] = o;
        }
        __syncwarp();
    }
}

// ---------------- linear1: F1c = [rh|x] @ W1a[2], fp16 out ----------------
__global__ void linear1_kernel(const float* __restrict__ s0, const float* __restrict__ s1,
                               const float* __restrict__ Wc, __half2* __restrict__ oC)
{
    extern __shared__ float sm[];
    float* sW = sm;                          // 8192 floats (u64 view: pairs)
    float2* sF2 = (float2*)(sm + 8192);      // 32KB dup'd acts
    int tid = threadIdx.x, w = tid>>5, L = tid&31;
    for (int i = tid; i < 8192; i += blockDim.x) sW[i] = Wc[i];
    __syncthreads();
    const u64* sW64 = (const u64*)sW;
    float2* f = sF2 + w*(PT*128);
    const u64* f64 = (const u64*)f;
    for (int t = blockIdx.x*NWARP + w; t < NTASK; t += gridDim.x*NWARP) {
        int p0 = t*PT;
        #pragma unroll
        for (int q = 0; q < PT; q++) {
            int p = p0 + q;
            float v0 = s0[(size_t)p*64 + L],  v1 = s0[(size_t)p*64 + 32 + L];
            float v2 = s1[(size_t)p*64 + L],  v3 = s1[(size_t)p*64 + 32 + L];
            f[q*128 + L]      = make_float2(v0, v0);
            f[q*128 + 32 + L] = make_float2(v1, v1);
            f[q*128 + 64 + L] = make_float2(v2, v2);
            f[q*128 + 96 + L] = make_float2(v3, v3);
        }
        __syncwarp();
        u64 acc[PT];
        #pragma unroll
        for (int q = 0; q < PT; q++) acc[q] = 0ull;
        #pragma unroll 8
        for (int c = 0; c < 128; c++) {
            u64 wv = sW64[c*32 + L];
            #pragma unroll
            for (int q = 0; q < PT; q++)
                acc[q] = ffma2(f64[q*128 + c], wv, acc[q]);
        }
        #pragma unroll
        for (int q = 0; q < PT; q++) {
            float2 r = upk(acc[q]);
            oC[(size_t)(p0+q)*32 + L] = __floats2half2_rn(r.x, r.y);
        }
        __syncwarp();
    }
}

// ---------------- gate01: branches 0+1 -> z, r*h ----------------
__global__ void gate01_kernel(const float* __restrict__ h,
    const float* __restrict__ W1, const float* __restrict__ b1,
    const float* __restrict__ W2, const float* __restrict__ b2,
    const float* __restrict__ W3, const float* __restrict__ b3,
    const int* __restrict__ nidx, const float* __restrict__ ef,
    float* __restrict__ z_out, float* __restrict__ rh_out)
{
    extern __shared__ float sm[];
    float4* sW2 = (float4*)sm;               // 64*32 float4 {a0,a1,b0,b1} = 32KB
    float4* sW3 = (float4*)(sm + 8192);      // 32KB
    float4* sStg = (float4*)(sm + 16384);    // NWARP * 256 float4 = 32KB
    int tid = threadIdx.x, w = tid>>5, L = tid&31;
    for (int i = tid; i < 2048; i += blockDim.x) {
        int j = i >> 5, l = i & 31;
        float4 w2, w3;
        w2.x = W2[j*64 + 2*l];        w2.y = W2[j*64 + 2*l + 1];
        w2.z = W2[4096 + j*64 + 2*l]; w2.w = W2[4096 + j*64 + 2*l + 1];
        sW2[i] = w2;
        w3.x = W3[j*64 + 2*l];        w3.y = W3[j*64 + 2*l + 1];
        w3.z = W3[4096 + j*64 + 2*l]; w3.w = W3[4096 + j*64 + 2*l + 1];
        sW3[i] = w3;
    }
    __syncthreads();

    const float* eWa = W1 + 128*64;                // branch 0 edge rows
    const float* eWb = W1 + 131*64 + 128*64;       // branch 1 edge rows
    __half2 wA[3], wB[3];
    #pragma unroll
    for (int j = 0; j < 3; j++) {
        wA[j] = __floats2half2_rn(eWa[j*64 + 2*L], eWa[j*64 + 2*L + 1]);
        wB[j] = __floats2half2_rn(eWb[j*64 + 2*L], eWb[j*64 + 2*L + 1]);
    }
    float2 b1a = *(const float2*)&b1[2*L],      b1b = *(const float2*)&b1[64 + 2*L];
    float2 b2a = *(const float2*)&b2[2*L],      b2b = *(const float2*)&b2[64 + 2*L];
    float2 b3a = *(const float2*)&b3[2*L],      b3b = *(const float2*)&b3[64 + 2*L];
    u64 i2a = pk2(b2a.x, b2a.y), i2b = pk2(b2b.x, b2b.y);
    u64 i3a = pk2(b3a.x, b3a.y), i3b = pk2(b3b.x, b3b.y);

    float4* stg = sStg + w*256;   // [q*64 + j] = {pa,pa,pb,pb}
    for (int t = blockIdx.x*NWARP + w; t < NTASK; t += gridDim.x*NWARP) {
        int p0 = t*PT;
        int bb = p0 >> 13;
        const uint2* Fab = g_F1ab + (size_t)bb*NN*32;
        #pragma unroll
        for (int q = 0; q < PT; q++) {
            int p = p0 + q;
            int ii = nidx[(size_t)p*KK + L];
            // lane k owns neighbor k's edge triple, pre-packed fp16
            unsigned e01, e2d;
            {
                const float* ep = ef + (size_t)p*96 + 3*L;
                __half2 t01 = __floats2half2_rn(ep[0], ep[1]);
                __half2 t2  = __float2half2_rn(ep[2]);
                e01 = *(const unsigned*)&t01;
                e2d = *(const unsigned*)&t2;
            }
            __half2 ma = __float2half2_rn(-6.0e4f), mb = ma;
            #pragma unroll
            for (int k = 0; k < KK; k++) {
                int fi       = __shfl_sync(0xffffffffu, ii,  k);
                unsigned p01 = __shfl_sync(0xffffffffu, e01, k);
                unsigned p2  = __shfl_sync(0xffffffffu, e2d, k);
                __half2 he01 = *(const __half2*)&p01;
                __half2 h0 = __low2half2(he01), h1 = __high2half2(he01);
                __half2 h2v = *(const __half2*)&p2;
                uint2 v = __ldg(&Fab[(size_t)fi*32 + L]);
                __half2 ta = *(const __half2*)&v.x;
                ta = __hfma2(h0, wA[0], ta);
                ta = __hfma2(h1, wA[1], ta);
                ta = __hfma2(h2v, wA[2], ta);
                ma = __hmax2(ma, ta);
                __half2 tb = *(const __half2*)&v.y;
                tb = __hfma2(h0, wB[0], tb);
                tb = __hfma2(h1, wB[1], tb);
                tb = __hfma2(h2v, wB[2], tb);
                mb = __hmax2(mb, tb);
            }
            float2 fa = __half22float2(ma), fb = __half22float2(mb);
            fa.x = lrelu(fa.x + b1a.x);  fa.y = lrelu(fa.y + b1a.y);
            fb.x = lrelu(fb.x + b1b.x);  fb.y = lrelu(fb.y + b1b.y);
            stg[q*64 + 2*L]     = make_float4(fa.x, fa.x, fb.x, fb.x);
            stg[q*64 + 2*L + 1] = make_float4(fa.y, fa.y, fb.y, fb.y);
        }
        __syncwarp();
        // layer 1
        u64 ya[PT], yb[PT];
        #pragma unroll
        for (int q = 0; q < PT; q++) { ya[q] = i2a; yb[q] = i2b; }
        #pragma unroll 8
        for (int j = 0; j < 64; j++) {
            float4 wv = sW2[j*32 + L];
            u64 wa = pk2(wv.x, wv.y), wb = pk2(wv.z, wv.w);
            #pragma unroll
            for (int q = 0; q < PT; q++) {
                float4 av = stg[q*64 + j];
                ya[q] = ffma2(pk2(av.x, av.y), wa, ya[q]);
                yb[q] = ffma2(pk2(av.z, av.w), wb, yb[q]);
            }
        }
        __syncwarp();
        #pragma unroll
        for (int q = 0; q < PT; q++) {
            float2 A = upk(ya[q]), Bv = upk(yb[q]);
            A.x = lrelu(A.x);  A.y = lrelu(A.y);
            Bv.x = lrelu(Bv.x); Bv.y = lrelu(Bv.y);
            stg[q*64 + 2*L]     = make_float4(A.x, A.x, Bv.x, Bv.x);
            stg[q*64 + 2*L + 1] = make_float4(A.y, A.y, Bv.y, Bv.y);
        }
        __syncwarp();
        // layer 2
        u64 oa[PT], ob[PT];
        #pragma unroll
        for (int q = 0; q < PT; q++) { oa[q] = i3a; ob[q] = i3b; }
        #pragma unroll 8
        for (int j = 0; j < 64; j++) {
            float4 wv = sW3[j*32 + L];
            u64 wa = pk2(wv.x, wv.y), wb = pk2(wv.z, wv.w);
            #pragma unroll
            for (int q = 0; q < PT; q++) {
                float4 av = stg[q*64 + j];
                oa[q] = ffma2(pk2(av.x, av.y), wa, oa[q]);
                ob[q] = ffma2(pk2(av.z, av.w), wb, ob[q]);
            }
        }
        #pragma unroll
        for (int q = 0; q < PT; q++) {
            int p = p0 + q;
            float2 A = upk(oa[q]), Bv = upk(ob[q]);
            float z0 = sigm(A.x), z1 = sigm(A.y);
            *(float2*)&z_out[(size_t)p*64 + 2*L] = make_float2(z0, z1);
            float r0 = sigm(Bv.x), r1 = sigm(Bv.y);
            float2 hv = *(const float2*)&h[(size_t)p*64 + 2*L];
            *(float2*)&rh_out[(size_t)p*64 + 2*L] = make_float2(r0*hv.x, r1*hv.y);
        }
        __syncwarp();
    }
}

// ---------------- gate2: branch 2 -> q; out = h + z*(q-h) ----------------
__global__ void gate2_kernel(const float* __restrict__ h,
    const float* __restrict__ W1, const float* __restrict__ b1,
    const float* __restrict__ W2, const float* __restrict__ b2,
    const float* __restrict__ W3, const float* __restrict__ b3,
    const int* __restrict__ nidx, const float* __restrict__ ef,
    float* __restrict__ out)
{
    extern __shared__ float sm[];
    float* sW2 = sm;                         // 4096 floats (u64 pairs)
    float* sW3 = sm + 4096;                  // 4096
    float2* sStg = (float2*)(sm + 8192);     // NWARP * 256 float2 = 16KB
    int tid = threadIdx.x, w = tid>>5, L = tid&31;
    for (int i = tid; i < 4096; i += blockDim.x) {
        sW2[i] = W2[2*4096 + i];
        sW3[i] = W3[2*4096 + i];
    }
    __syncthreads();
    const u64* sW2u = (const u64*)sW2;
    const u64* sW3u = (const u64*)sW3;

    const float* eWc = W1 + 2*131*64 + 128*64;
    __half2 wC[3];
    #pragma unroll
    for (int j = 0; j < 3; j++)
        wC[j] = __floats2half2_rn(eWc[j*64 + 2*L], eWc[j*64 + 2*L + 1]);
    float2 b1c = *(const float2*)&b1[128 + 2*L];
    float2 b2c = *(const float2*)&b2[128 + 2*L];
    float2 b3c = *(const float2*)&b3[128 + 2*L];
    u64 i2c = pk2(b2c.x, b2c.y), i3c = pk2(b3c.x, b3c.y);

    float2* stg = sStg + w*256;
    const u64* stgu = (const u64*)stg;
    for (int t = blockIdx.x*NWARP + w; t < NTASK; t += gridDim.x*NWARP) {
        int p0 = t*PT;
        int bb = p0 >> 13;
        const __half2* Fc = g_F1c + (size_t)bb*NN*32;
        #pragma unroll
        for (int q = 0; q < PT; q++) {
            int p = p0 + q;
            int ii = nidx[(size_t)p*KK + L];
            unsigned e01, e2d;
            {
                const float* ep = ef + (size_t)p*96 + 3*L;
                __half2 t01 = __floats2half2_rn(ep[0], ep[1]);
                __half2 t2  = __float2half2_rn(ep[2]);
                e01 = *(const unsigned*)&t01;
                e2d = *(const unsigned*)&t2;
            }
            __half2 mc = __float2half2_rn(-6.0e4f);
            #pragma unroll
            for (int k = 0; k < KK; k++) {
                int fi       = __shfl_sync(0xffffffffu, ii,  k);
                unsigned p01 = __shfl_sync(0xffffffffu, e01, k);
                unsigned p2  = __shfl_sync(0xffffffffu, e2d, k);
                __half2 he01 = *(const __half2*)&p01;
                __half2 h0 = __low2half2(he01), h1 = __high2half2(he01);
                __half2 h2v = *(const __half2*)&p2;
                __half2 v = __ldg(&Fc[(size_t)fi*32 + L]);
                v = __hfma2(h0, wC[0], v);
                v = __hfma2(h1, wC[1], v);
                v = __hfma2(h2v, wC[2], v);
                mc = __hmax2(mc, v);
            }
            float2 fc = __half22float2(mc);
            fc.x = lrelu(fc.x + b1c.x);  fc.y = lrelu(fc.y + b1c.y);
            stg[q*64 + 2*L]     = make_float2(fc.x, fc.x);
            stg[q*64 + 2*L + 1] = make_float2(fc.y, fc.y);
        }
        __syncwarp();
        u64 yc[PT];
        #pragma unroll
        for (int q = 0; q < PT; q++) yc[q] = i2c;
        #pragma unroll 8
        for (int j = 0; j < 64; j++) {
            u64 wv = sW2u[j*32 + L];
            #pragma unroll
            for (int q = 0; q < PT; q++)
                yc[q] = ffma2(stgu[q*64 + j], wv, yc[q]);
        }
        __syncwarp();
        #pragma unroll
        for (int q = 0; q < PT; q++) {
            float2 A = upk(yc[q]);
            A.x = lrelu(A.x);  A.y = lrelu(A.y);
            stg[q*64 + 2*L]     = make_float2(A.x, A.x);
            stg[q*64 + 2*L + 1] = make_float2(A.y, A.y);
        }
        __syncwarp();
        u64 oc[PT];
        #pragma unroll
        for (int q = 0; q < PT; q++) oc[q] = i3c;
        #pragma unroll 8
        for (int j = 0; j < 64; j++) {
            u64 wv = sW3u[j*32 + L];
            #pragma unroll
            for (int q = 0; q < PT; q++)
                oc[q] = ffma2(stgu[q*64 + j], wv, oc[q]);
        }
        #pragma unroll
        for (int q = 0; q < PT; q++) {
            int p = p0 + q;
            float2 A = upk(oc[q]);
            float q0 = tanhf(A.x), q1 = tanhf(A.y);
            float2 zv = *(const float2*)&g_z[(size_t)p*64 + 2*L];
            float2 hv = *(const float2*)&h[(size_t)p*64 + 2*L];
            float o0 = hv.x + zv.x*(q0 - hv.x);
            float o1 = hv.y + zv.y*(q1 - hv.y);
            *(float2*)&out[(size_t)p*64 + 2*L] = make_float2(o0, o1);
        }
        __syncwarp();
    }
}

extern "C" void kernel_launch(void* const* d_in, const int* in_sizes, int n_in,
                              void* d_out, int out_size)
{
    const float* h   = (const float*)d_in[0];
    const float* x   = (const float*)d_in[1];
    // d_in[2] = c, unused (matches reference)
    const float* W1  = (const float*)d_in[3];
    const float* b1  = (const float*)d_in[4];
    const float* W2  = (const float*)d_in[5];
    const float* b2  = (const float*)d_in[6];
    const float* W3  = (const float*)d_in[7];
    const float* b3  = (const float*)d_in[8];
    const int*   nidx = (const int*)d_in[9];
    const float* ef  = (const float*)d_in[10];
    float* out = (float*)d_out;

    void *pF1ab, *pF1c, *pz, *prh;
    cudaGetSymbolAddress(&pF1ab, g_F1ab);
    cudaGetSymbolAddress(&pF1c,  g_F1c);
    cudaGetSymbolAddress(&pz,    g_z);
    cudaGetSymbolAddress(&prh,   g_rh);

    const int smem_lin2 = (16384 + 8192) * 4;   // 96KB
    const int smem_lin1 = (8192 + 8192) * 4;    // 64KB
    const int smem_g01  = (16384 + 8192) * 4;   // 96KB
    const int smem_g2   = (8192 + 4096) * 4;    // 48KB

    cudaFuncSetAttribute(linear2_kernel, cudaFuncAttributeMaxDynamicSharedMemorySize, smem_lin2);
    cudaFuncSetAttribute(linear1_kernel, cudaFuncAttributeMaxDynamicSharedMemorySize, smem_lin1);
    cudaFuncSetAttribute(gate01_kernel,  cudaFuncAttributeMaxDynamicSharedMemorySize, smem_g01);
    cudaFuncSetAttribute(gate2_kernel,   cudaFuncAttributeMaxDynamicSharedMemorySize, smem_g2);

    dim3 blk(256);

    // F1ab = [h|x] @ {W1a[0], W1a[1]}  (packed fp16)
    linear2_kernel<<<296, blk, smem_lin2>>>(h, x, W1, W1 + 131*64, (uint2*)pF1ab);
    // z, r*h
    gate01_kernel<<<296, blk, smem_g01>>>(h, W1, b1, W2, b2, W3, b3, nidx, ef,
                                          (float*)pz, (float*)prh);
    // F1c = [r*h|x] @ W1a[2]  (fp16)
    linear1_kernel<<<444, blk, smem_lin1>>>((const float*)prh, x, W1 + 2*131*64, (__half2*)pF1c);
    // q and final output
    gate2_kernel<<<592, blk, smem_g2>>>(h, W1, b1, W2, b2, W3, b3, nidx, ef, out);
}